// round 1
// baseline (speedup 1.0000x reference)
#include <cuda_runtime.h>
#include <cstdint>

#define NCOUNT 8
#define B_TOTAL 16384
#define L1 3072
#define NOUT 16            // L2+1
#define M_TILE 128
#define KCHUNK 64
#define NCHUNK (L1 / KCHUNK)               // 48
#define MAX_TILES (B_TOTAL / M_TILE + NCOUNT)  // 136

// ---------------- device scratch (no allocations allowed) ----------------
__device__ int   g_count[NCOUNT];
__device__ int   g_fill[NCOUNT];
__device__ int   g_offset[NCOUNT + 1];
__device__ int   g_rows[B_TOTAL];
__device__ int   g_tile_bucket[MAX_TILES];
__device__ int   g_tile_start[MAX_TILES];
__device__ int   g_tile_rows[MAX_TILES];
__device__ int   g_ntiles;
__device__ float g_wcomb[NCOUNT * NOUT * L1];   // 1.5 MB, combined l1_w[bucket]+l1f_w

// ---------------- packed f32x2 FMA ----------------
#define FMA2(d, a, b) asm("fma.rn.f32x2 %0, %1, %2, %0;" : "+l"(d) : "l"(a), "l"(b))

// ---------------- prep kernels ----------------
__global__ void k_zero() {
    if (threadIdx.x < NCOUNT) { g_count[threadIdx.x] = 0; g_fill[threadIdx.x] = 0; }
}

__global__ void k_count(const int* __restrict__ idx) {
    int i = blockIdx.x * blockDim.x + threadIdx.x;
    if (i < B_TOTAL) atomicAdd(&g_count[idx[i]], 1);
}

__global__ void k_build() {
    if (threadIdx.x == 0 && blockIdx.x == 0) {
        int off = 0, t = 0;
        for (int c = 0; c < NCOUNT; c++) {
            g_offset[c] = off;
            int n = g_count[c];
            for (int s = 0; s < n; s += M_TILE) {
                g_tile_bucket[t] = c;
                g_tile_start[t]  = off + s;
                g_tile_rows[t]   = (n - s < M_TILE) ? (n - s) : M_TILE;
                t++;
            }
            off += n;
        }
        g_offset[NCOUNT] = off;
        g_ntiles = t;
    }
}

__global__ void k_scatter(const int* __restrict__ idx) {
    int i = blockIdx.x * blockDim.x + threadIdx.x;
    if (i < B_TOTAL) {
        int c = idx[i];
        int p = atomicAdd(&g_fill[c], 1);
        g_rows[g_offset[c] + p] = i;
    }
}

__global__ void k_comb(const float* __restrict__ l1w, const float* __restrict__ l1fw) {
    int e = blockIdx.x * blockDim.x + threadIdx.x;   // [c][j][k] flat == l1_w layout
    if (e < NCOUNT * NOUT * L1) {
        int k = e % L1;
        int r = (e / L1) % NOUT;
        g_wcomb[e] = l1w[e] + l1fw[r * L1 + k];
    }
}

// ---------------- main fused kernel ----------------
// dyn smem: sx[2][2048] float4 (x tile, swizzled) then sw[2][256] float4 (w tile)
extern __shared__ float4 s_dyn[];

__global__ void __launch_bounds__(128, 1)
k_main(const float* __restrict__ x,
       const float* __restrict__ l1b, const float* __restrict__ l1fb,
       const float* __restrict__ l2w, const float* __restrict__ l2b,
       const float* __restrict__ outw, const float* __restrict__ outb,
       float* __restrict__ out)
{
    int tile = blockIdx.x;
    if (tile >= g_ntiles) return;
    const int bucket = g_tile_bucket[tile];
    const int start  = g_tile_start[tile];
    const int rows   = g_tile_rows[tile];
    const int tid    = threadIdx.x;

    __shared__ int   s_rows[M_TILE];
    __shared__ float s_wpad[32 * 32];       // l2 weights padded 30->32
    __shared__ float s_outw[32];
    __shared__ float s_l2b[32];
    __shared__ float s_bc[16];
    __shared__ float s_outb;

    if (tid < M_TILE) {
        int mi = tid < rows ? tid : rows - 1;
        s_rows[tid] = g_rows[start + mi];
    }
#pragma unroll
    for (int i = 0; i < 8; i++) {
        int e = tid + 128 * i;
        int o = e >> 5, j = e & 31;
        s_wpad[e] = (j < 30) ? l2w[(bucket * 32 + o) * 30 + j] : 0.f;
    }
    if (tid < 32) {
        s_outw[tid] = outw[bucket * 32 + tid];
        s_l2b[tid]  = l2b[bucket * 32 + tid];
    }
    if (tid < 16) s_bc[tid] = l1b[bucket * 16 + tid] + l1fb[tid];
    if (tid == 0) s_outb = outb[bucket];
    __syncthreads();

    float4* sx = s_dyn;            // 2 * 2048 float4 = 64 KB
    float4* sw = s_dyn + 4096;     // 2 * 256  float4 = 8 KB

    // loader assignment (fixed per thread)
    const int k4l = tid & 15;      // float4 index within 64-float chunk row
    const int mb  = tid >> 4;      // 0..7

    unsigned sx0 = (unsigned)__cvta_generic_to_shared(sx);
    unsigned sw0 = (unsigned)__cvta_generic_to_shared(sw);

    // compute assignment
    const int ks = tid >> 5;           // k-split warp 0..3
    const int ng = (tid >> 4) & 1;     // 0..1 -> 8 cols each
    const int mg = tid & 15;           // 0..15 -> 8 rows each
    const int m0 = mg * 8;
    const int j0 = ng * 8;

    unsigned long long acc[8][8];
#pragma unroll
    for (int r = 0; r < 8; r++)
#pragma unroll
        for (int s = 0; s < 8; s++) acc[r][s] = 0ull;

#define ISSUE_CHUNK(cc, bb)                                                            \
    do {                                                                               \
        int k0_ = (cc) * KCHUNK;                                                       \
        unsigned sxb_ = sx0 + (unsigned)(bb) * 2048u * 16u;                            \
        _Pragma("unroll")                                                              \
        for (int i_ = 0; i_ < 16; i_++) {                                              \
            int m_ = mb + 8 * i_;                                                      \
            const float* src_ = x + (size_t)s_rows[m_] * L1 + k0_ + k4l * 4;           \
            unsigned dst_ = sxb_ + (unsigned)((m_ * 16 + (k4l ^ i_)) * 16);            \
            asm volatile("cp.async.cg.shared.global [%0], [%1], 16;\n"                 \
                         :: "r"(dst_), "l"(src_));                                     \
        }                                                                              \
        unsigned swb_ = sw0 + (unsigned)(bb) * 256u * 16u;                             \
        _Pragma("unroll")                                                              \
        for (int i_ = 0; i_ < 2; i_++) {                                               \
            int wi_ = tid + 128 * i_;                                                  \
            int j_  = wi_ >> 4;                                                        \
            int kk_ = wi_ & 15;                                                        \
            const float* src_ = g_wcomb + (size_t)(bucket * 16 + j_) * L1 + k0_ + kk_ * 4; \
            unsigned dst_ = swb_ + (unsigned)((j_ * 16 + kk_) * 16);                   \
            asm volatile("cp.async.cg.shared.global [%0], [%1], 16;\n"                 \
                         :: "r"(dst_), "l"(src_));                                     \
        }                                                                              \
        asm volatile("cp.async.commit_group;\n");                                      \
    } while (0)

    ISSUE_CHUNK(0, 0);

    for (int c = 0; c < NCHUNK; c++) {
        if (c + 1 < NCHUNK) {
            ISSUE_CHUNK(c + 1, (c + 1) & 1);
            asm volatile("cp.async.wait_group 1;\n");
        } else {
            asm volatile("cp.async.wait_group 0;\n");
        }
        __syncthreads();

        const ulonglong2* xb = (const ulonglong2*)(sx + (c & 1) * 2048);
        const ulonglong2* wb = (const ulonglong2*)(sw + (c & 1) * 256);

#pragma unroll
        for (int i = 0; i < 4; i++) {
            int k4 = ks * 4 + i;
            ulonglong2 wv[8];
#pragma unroll
            for (int s = 0; s < 8; s++) wv[s] = wb[(j0 + s) * 16 + k4];
            int swk4 = k4 ^ mg;   // (m>>3)&15 == mg for m = mg*8 + r
#pragma unroll
            for (int r = 0; r < 8; r++) {
                ulonglong2 xv = xb[(m0 + r) * 16 + swk4];
#pragma unroll
                for (int s = 0; s < 8; s++) {
                    FMA2(acc[r][s], xv.x, wv[s].x);
                    FMA2(acc[r][s], xv.y, wv[s].y);
                }
            }
        }
        __syncthreads();
    }

    // ---- reduce k-split partials via smem (overlay on pipeline buffers) ----
    float* accs = (float*)s_dyn;   // 4 * 128 * 17 floats = 34816 B
#pragma unroll
    for (int r = 0; r < 8; r++)
#pragma unroll
        for (int s = 0; s < 8; s++) {
            union { unsigned long long u; float2 f; } cv;
            cv.u = acc[r][s];
            accs[ks * 2176 + (m0 + r) * 17 + (j0 + s)] = cv.f.x + cv.f.y;
        }
    __syncthreads();

    // ---- fused stage 2/3: one row per thread ----
    float t[16];
#pragma unroll
    for (int j = 0; j < 16; j++) {
        t[j] = accs[0 * 2176 + tid * 17 + j] + accs[1 * 2176 + tid * 17 + j]
             + accs[2 * 2176 + tid * 17 + j] + accs[3 * 2176 + tid * 17 + j]
             + s_bc[j];
    }

    float v[32];
#pragma unroll
    for (int j = 0; j < 15; j++) {
        float a = t[j];
        v[j]      = fminf(a * a * (127.0f / 128.0f), 1.0f);
        v[15 + j] = fminf(fmaxf(a, 0.0f), 1.0f);
    }
    v[30] = 0.f; v[31] = 0.f;

    float res = t[15] + s_outb;
    const float4* wp4 = (const float4*)s_wpad;
#pragma unroll
    for (int o = 0; o < 32; o++) {
        float s = s_l2b[o];
#pragma unroll
        for (int q = 0; q < 8; q++) {
            float4 w = wp4[o * 8 + q];
            s += w.x * v[q * 4] + w.y * v[q * 4 + 1] + w.z * v[q * 4 + 2] + w.w * v[q * 4 + 3];
        }
        s = fminf(fmaxf(s, 0.0f), 1.0f);
        res += s * s_outw[o];
    }

    if (tid < rows) out[s_rows[tid]] = res;
}

// ---------------- launcher ----------------
extern "C" void kernel_launch(void* const* d_in, const int* in_sizes, int n_in,
                              void* d_out, int out_size)
{
    const float* x     = (const float*)d_in[0];
    const int*   idx   = (const int*)  d_in[1];
    const float* l1w   = (const float*)d_in[2];
    const float* l1b   = (const float*)d_in[3];
    const float* l1fw  = (const float*)d_in[4];
    const float* l1fb  = (const float*)d_in[5];
    const float* l2w   = (const float*)d_in[6];
    const float* l2b   = (const float*)d_in[7];
    const float* outw  = (const float*)d_in[8];
    const float* outb  = (const float*)d_in[9];
    float* out = (float*)d_out;

    static bool attr_set = false;
    if (!attr_set) {
        cudaFuncSetAttribute(k_main, cudaFuncAttributeMaxDynamicSharedMemorySize, 73728);
        attr_set = true;
    }

    k_zero<<<1, 32>>>();
    k_count<<<B_TOTAL / 512, 512>>>(idx);
    k_build<<<1, 32>>>();
    k_scatter<<<B_TOTAL / 512, 512>>>(idx);
    k_comb<<<(NCOUNT * NOUT * L1) / 512, 512>>>(l1w, l1fw);
    k_main<<<MAX_TILES, 128, 73728>>>(x, l1b, l1fb, l2w, l2b, outw, outb, out);
}

// round 2
// speedup vs baseline: 1.1438x; 1.1438x over previous
#include <cuda_runtime.h>
#include <cstdint>

#define NCOUNT 8
#define B_TOTAL 16384
#define L1 3072
#define NOUT 16            // L2+1
#define M_TILE 128
#define KCHUNK 128
#define NCHUNK (L1 / KCHUNK)               // 24
#define MAX_TILES (B_TOTAL / M_TILE + NCOUNT)  // 136
#define NTHREADS 256

// ---------------- device scratch (no allocations allowed) ----------------
__device__ int   g_count[NCOUNT];
__device__ int   g_fill[NCOUNT];
__device__ int   g_offset[NCOUNT + 1];
__device__ int   g_rows[B_TOTAL];
__device__ int   g_tile_bucket[MAX_TILES];
__device__ int   g_tile_start[MAX_TILES];
__device__ int   g_tile_rows[MAX_TILES];
__device__ int   g_ntiles;
__device__ float g_wcomb[NCOUNT * NOUT * L1];   // 1.5 MB, combined l1_w[bucket]+l1f_w

// ---------------- packed f32x2 FMA ----------------
#define FMA2(d, a, b) asm("fma.rn.f32x2 %0, %1, %2, %0;" : "+l"(d) : "l"(a), "l"(b))

// ---------------- prep kernels ----------------
// fused: zero counters + build combined weights
__global__ void k_pre(const float* __restrict__ l1w, const float* __restrict__ l1fw) {
    int e = blockIdx.x * blockDim.x + threadIdx.x;
    if (blockIdx.x == 0 && threadIdx.x < NCOUNT) {
        g_count[threadIdx.x] = 0; g_fill[threadIdx.x] = 0;
    }
    if (e < NCOUNT * NOUT * L1) {
        int k = e % L1;
        int r = (e / L1) % NOUT;
        g_wcomb[e] = l1w[e] + l1fw[r * L1 + k];
    }
}

__global__ void k_count(const int* __restrict__ idx) {
    int i = blockIdx.x * blockDim.x + threadIdx.x;
    int lane = threadIdx.x & 31;
    if (i < B_TOTAL) {
        int c = idx[i];
        unsigned mask = __match_any_sync(0xffffffffu, c);
        int leader = __ffs(mask) - 1;
        if (lane == leader) atomicAdd(&g_count[c], __popc(mask));
    }
}

__global__ void k_build() {
    if (threadIdx.x == 0 && blockIdx.x == 0) {
        int off = 0, t = 0;
        for (int c = 0; c < NCOUNT; c++) {
            g_offset[c] = off;
            int n = g_count[c];
            for (int s = 0; s < n; s += M_TILE) {
                g_tile_bucket[t] = c;
                g_tile_start[t]  = off + s;
                g_tile_rows[t]   = (n - s < M_TILE) ? (n - s) : M_TILE;
                t++;
            }
            off += n;
        }
        g_offset[NCOUNT] = off;
        g_ntiles = t;
    }
}

__global__ void k_scatter(const int* __restrict__ idx) {
    int i = blockIdx.x * blockDim.x + threadIdx.x;
    int lane = threadIdx.x & 31;
    if (i < B_TOTAL) {
        int c = idx[i];
        unsigned mask = __match_any_sync(0xffffffffu, c);
        int leader = __ffs(mask) - 1;
        int rank = __popc(mask & ((1u << lane) - 1u));
        int base = 0;
        if (lane == leader) base = atomicAdd(&g_fill[c], __popc(mask));
        base = __shfl_sync(mask, base, leader);
        g_rows[g_offset[c] + base + rank] = i;
    }
}

// ---------------- main fused kernel ----------------
// dyn smem: sx[2][128][32] float4 (x tile, swizzled) = 128KB, then sw[2][16][32] float4 = 16KB
extern __shared__ float4 s_dyn[];

__global__ void __launch_bounds__(NTHREADS, 1)
k_main(const float* __restrict__ x,
       const float* __restrict__ l1b, const float* __restrict__ l1fb,
       const float* __restrict__ l2w, const float* __restrict__ l2b,
       const float* __restrict__ outw, const float* __restrict__ outb,
       float* __restrict__ out)
{
    int tile = blockIdx.x;
    if (tile >= g_ntiles) return;
    const int bucket = g_tile_bucket[tile];
    const int start  = g_tile_start[tile];
    const int rows   = g_tile_rows[tile];
    const int tid    = threadIdx.x;

    __shared__ int   s_rows[M_TILE];
    __shared__ float s_wpad[32 * 32];       // l2 weights padded 30->32
    __shared__ float s_outw[32];
    __shared__ float s_l2b[32];
    __shared__ float s_bc[16];
    __shared__ float s_outb;

    if (tid < M_TILE) {
        int mi = tid < rows ? tid : rows - 1;
        s_rows[tid] = g_rows[start + mi];
    }
#pragma unroll
    for (int i = 0; i < 4; i++) {
        int e = tid + NTHREADS * i;
        int o = e >> 5, j = e & 31;
        s_wpad[e] = (j < 30) ? l2w[(bucket * 32 + o) * 30 + j] : 0.f;
    }
    if (tid < 32) {
        s_outw[tid] = outw[bucket * 32 + tid];
        s_l2b[tid]  = l2b[bucket * 32 + tid];
    }
    if (tid < 16) s_bc[tid] = l1b[bucket * 16 + tid] + l1fb[tid];
    if (tid == 0) s_outb = outb[bucket];
    __syncthreads();

    float4* sx = s_dyn;            // 2 * 4096 float4 = 128 KB
    float4* sw = s_dyn + 8192;     // 2 * 512  float4 = 16 KB

    // loader assignment (fixed per thread)
    const int kkl = tid & 31;      // float4 index within 128-float chunk row
    const int mb  = tid >> 5;      // 0..7

    unsigned sx0 = (unsigned)__cvta_generic_to_shared(sx);
    unsigned sw0 = (unsigned)__cvta_generic_to_shared(sw);

    // compute assignment: 8 warps = 8 k-split groups
    const int ks = tid >> 5;           // k-split warp 0..7
    const int ng = (tid >> 4) & 1;     // 0..1 -> 8 cols each
    const int mg = tid & 15;           // 0..15 -> 8 rows each
    const int m0 = mg * 8;
    const int j0 = ng * 8;

    unsigned long long acc[8][8];
#pragma unroll
    for (int r = 0; r < 8; r++)
#pragma unroll
        for (int s = 0; s < 8; s++) acc[r][s] = 0ull;

#define ISSUE_CHUNK(cc, bb)                                                            \
    do {                                                                               \
        int k0_ = (cc) * KCHUNK;                                                       \
        unsigned sxb_ = sx0 + (unsigned)(bb) * 4096u * 16u;                            \
        _Pragma("unroll")                                                              \
        for (int i_ = 0; i_ < 16; i_++) {                                              \
            int m_ = mb + 8 * i_;                                                      \
            const float* src_ = x + (size_t)s_rows[m_] * L1 + k0_ + kkl * 4;           \
            unsigned dst_ = sxb_ + (unsigned)((m_ * 32 + (kkl ^ i_)) * 16);            \
            asm volatile("cp.async.cg.shared.global [%0], [%1], 16;\n"                 \
                         :: "r"(dst_), "l"(src_));                                     \
        }                                                                              \
        unsigned swb_ = sw0 + (unsigned)(bb) * 512u * 16u;                             \
        _Pragma("unroll")                                                              \
        for (int i_ = 0; i_ < 2; i_++) {                                               \
            int wi_ = tid + NTHREADS * i_;                                             \
            int j_  = wi_ >> 5;                                                        \
            int kk_ = wi_ & 31;                                                        \
            const float* src_ = g_wcomb + (size_t)(bucket * 16 + j_) * L1 + k0_ + kk_ * 4; \
            unsigned dst_ = swb_ + (unsigned)((j_ * 32 + kk_) * 16);                   \
            asm volatile("cp.async.cg.shared.global [%0], [%1], 16;\n"                 \
                         :: "r"(dst_), "l"(src_));                                     \
        }                                                                              \
        asm volatile("cp.async.commit_group;\n");                                      \
    } while (0)

    ISSUE_CHUNK(0, 0);

    for (int c = 0; c < NCHUNK; c++) {
        if (c + 1 < NCHUNK) {
            ISSUE_CHUNK(c + 1, (c + 1) & 1);
            asm volatile("cp.async.wait_group 1;\n");
        } else {
            asm volatile("cp.async.wait_group 0;\n");
        }
        __syncthreads();

        const ulonglong2* xb = (const ulonglong2*)(sx + (c & 1) * 4096);
        const ulonglong2* wb = (const ulonglong2*)(sw + (c & 1) * 512);

#pragma unroll
        for (int i = 0; i < 4; i++) {
            int k4 = ks * 4 + i;                 // 0..31 across warps
            ulonglong2 wv[8];
#pragma unroll
            for (int s = 0; s < 8; s++) wv[s] = wb[(j0 + s) * 32 + k4];
            int swk = k4 ^ mg;                   // row-swizzle: (m>>3)&15 == mg
#pragma unroll
            for (int r = 0; r < 8; r++) {
                ulonglong2 xv = xb[(m0 + r) * 32 + swk];
#pragma unroll
                for (int s = 0; s < 8; s++) {
                    FMA2(acc[r][s], xv.x, wv[s].x);
                    FMA2(acc[r][s], xv.y, wv[s].y);
                }
            }
        }
        __syncthreads();
    }

    // ---- reduce k-split partials via smem (overlay on pipeline buffers) ----
    float* accs = (float*)s_dyn;   // 8 * 128 * 17 floats = 69632 B
#pragma unroll
    for (int r = 0; r < 8; r++)
#pragma unroll
        for (int s = 0; s < 8; s++) {
            union { unsigned long long u; float2 f; } cv;
            cv.u = acc[r][s];
            accs[ks * 2176 + (m0 + r) * 17 + (j0 + s)] = cv.f.x + cv.f.y;
        }
    __syncthreads();

    // ---- fused stage 2/3: one row per thread (first 128 threads) ----
    if (tid < M_TILE) {
        float t[16];
#pragma unroll
        for (int j = 0; j < 16; j++) {
            float a = 0.f;
#pragma unroll
            for (int p = 0; p < 8; p++) a += accs[p * 2176 + tid * 17 + j];
            t[j] = a + s_bc[j];
        }

        float v[32];
#pragma unroll
        for (int j = 0; j < 15; j++) {
            float a = t[j];
            v[j]      = fminf(a * a * (127.0f / 128.0f), 1.0f);
            v[15 + j] = fminf(fmaxf(a, 0.0f), 1.0f);
        }
        v[30] = 0.f; v[31] = 0.f;

        float res = t[15] + s_outb;
        const float4* wp4 = (const float4*)s_wpad;
#pragma unroll
        for (int o = 0; o < 32; o++) {
            float s = s_l2b[o];
#pragma unroll
            for (int q = 0; q < 8; q++) {
                float4 w = wp4[o * 8 + q];
                s += w.x * v[q * 4] + w.y * v[q * 4 + 1] + w.z * v[q * 4 + 2] + w.w * v[q * 4 + 3];
            }
            s = fminf(fmaxf(s, 0.0f), 1.0f);
            res += s * s_outw[o];
        }

        if (tid < rows) out[s_rows[tid]] = res;
    }
}

// ---------------- launcher ----------------
extern "C" void kernel_launch(void* const* d_in, const int* in_sizes, int n_in,
                              void* d_out, int out_size)
{
    const float* x     = (const float*)d_in[0];
    const int*   idx   = (const int*)  d_in[1];
    const float* l1w   = (const float*)d_in[2];
    const float* l1b   = (const float*)d_in[3];
    const float* l1fw  = (const float*)d_in[4];
    const float* l1fb  = (const float*)d_in[5];
    const float* l2w   = (const float*)d_in[6];
    const float* l2b   = (const float*)d_in[7];
    const float* outw  = (const float*)d_in[8];
    const float* outb  = (const float*)d_in[9];
    float* out = (float*)d_out;

    static bool attr_set = false;
    if (!attr_set) {
        cudaFuncSetAttribute(k_main, cudaFuncAttributeMaxDynamicSharedMemorySize, 147456);
        attr_set = true;
    }

    k_pre<<<(NCOUNT * NOUT * L1 + 511) / 512, 512>>>(l1w, l1fw);
    k_count<<<B_TOTAL / 512, 512>>>(idx);
    k_build<<<1, 32>>>();
    k_scatter<<<B_TOTAL / 512, 512>>>(idx);
    k_main<<<MAX_TILES, NTHREADS, 147456>>>(x, l1b, l1fb, l2w, l2b, outw, outb, out);
}